// round 5
// baseline (speedup 1.0000x reference)
#include <cuda_runtime.h>
#include <math.h>

// Problem: B=128, OUT=1024, IN=1024
// d_in: 0=input(128*1024) 1=weight(1024*1024) 2=bias(1024) 3=x0 4=dx 5=a 6=d
// out: (128,1024) float32
//
// res = mu + eps*sigma + bias collapses exactly to Yb + bias, where
// Yb = count of Bernoulli(p) successes under JAX partitionable threefry
// (verified bit-exact: rel_err == 0.0 in R3).
//
// R4: (1) threefry adds forced to IMAD (fma pipe) via opaque-reg mad.lo.u32
// — alu pipe was 94.9% binding, fma only 31.4%; (2) compare in scaled
// domain: k = bits>>9, kf = I2F(k), kf < x*(s*2^23) — exact (rounding
// commutes with power-of-2 scale; clip never binds for x in [0,1),
// s = sigmoid in (0,1); p==0 and p->1 edges agree).

#define B_DIM   128
#define OUT_DIM 1024
#define IN_DIM  1024

// Batch-independent synapse gain, pre-scaled: s23[o,i] = 2^23 * (d + a*sigmoid(dx*(w-x0))).
__device__ float g_s23[OUT_DIM * IN_DIM];

__global__ void prep_kernel(const float* __restrict__ w,
                            const float* __restrict__ x0,
                            const float* __restrict__ dx,
                            const float* __restrict__ a,
                            const float* __restrict__ d) {
    int idx = blockIdx.x * blockDim.x + threadIdx.x;  // exactly 1M threads
    float z = dx[idx] * (w[idx] - x0[idx]);
    float e = expf(-fabsf(z));
    float t = 1.0f / (1.0f + e);
    float sig = (z >= 0.0f) ? t : e * t;
    g_s23[idx] = (d[idx] + a[idx] * sig) * 8388608.0f;  // * 2^23, exact scale
}

// add via IMAD (fma pipe): d = a*one + b, with `one` opaque to ptxas so it
// cannot be strength-reduced back to IADD3 (alu pipe).
__device__ __forceinline__ unsigned int madd(unsigned int a, unsigned int b,
                                             unsigned int one) {
    unsigned int r;
    asm("mad.lo.u32 %0, %1, %2, %3;" : "=r"(r) : "r"(a), "r"(one), "r"(b));
    return r;
}

// 20-round threefry-2x32, key (0, 42); returns x0 ^ x1 (JAX partitionable fold).
// Round adds + key injections routed through IMAD; SHF/LOP3 stay on alu pipe.
__device__ __forceinline__ unsigned int tf20_xor(unsigned int x1, unsigned int one) {
    const unsigned int K1 = 42u;
    const unsigned int K2 = 0x1BD11BDAu ^ 42u;  // 0x1BD11BF0
    unsigned int x0 = 0u;
#define TFR(r) { x0 = madd(x1, x0, one); x1 = __funnelshift_l(x1, x1, (r)) ^ x0; }
    // initial key injection: x0 += 0 (elided); x1 += K1
    x1 = madd(x1, K1, one);
    TFR(13) TFR(15) TFR(26) TFR(6)
    x0 = madd(x0, K1, one);  x1 = madd(x1, K2 + 1u, one);
    TFR(17) TFR(29) TFR(16) TFR(24)
    x0 = madd(x0, K2, one);  x1 = madd(x1, 2u, one);
    TFR(13) TFR(15) TFR(26) TFR(6)
    /* x0 += 0 elided */     x1 = madd(x1, K1 + 3u, one);
    TFR(17) TFR(29) TFR(16) TFR(24)
    x0 = madd(x0, K1, one);  x1 = madd(x1, K2 + 4u, one);
    TFR(13) TFR(15) TFR(26) TFR(6)
    x0 = madd(x0, K2, one);  x1 = madd(x1, 5u, one);
#undef TFR
    return x0 ^ x1;
}

// One warp per output element (b, o). 8 warps/block share batch row b.
// lane handles 8 float4 chunks (32 samples): i = (k*32 + lane)*4 + c.
__global__ void __launch_bounds__(256)
synapse_kernel(const float* __restrict__ input,
               const float* __restrict__ bias,
               float* __restrict__ out) {
    const int warp = threadIdx.x >> 5;
    const int lane = threadIdx.x & 31;
    const int b = blockIdx.x >> 7;                    // 0..127
    const int o = ((blockIdx.x & 127) << 3) + warp;   // 0..1023

    unsigned int one;
    asm("mov.u32 %0, 1;" : "=r"(one));                // opaque 1

    const float bo = bias[o];

    const float4* __restrict__ inrow =
        reinterpret_cast<const float4*>(input + b * IN_DIM);
    const float4* __restrict__ srow =
        reinterpret_cast<const float4*>(g_s23 + o * IN_DIM);

    const unsigned int jbase = ((unsigned int)(b * OUT_DIM + o)) << 10;  // flat * IN_DIM

    int cnt = 0;
#pragma unroll 2
    for (int k = 0; k < 8; ++k) {
        const int v = (k << 5) + lane;      // float4 index within row, 0..255
        const float4 s4 = srow[v];
        const float4 x4 = inrow[v];
        const unsigned int j = jbase + ((unsigned int)v << 2);

        {
            float p23 = x4.x * s4.x;                       // = clip(x*s,0,1)*2^23 exactly
            unsigned int y = tf20_xor(j + 0u, one);
            float kf = __uint2float_rn(y >> 9);            // exact, < 2^23
            cnt += (kf < p23);                             // == (u < p) exactly
        }
        {
            float p23 = x4.y * s4.y;
            unsigned int y = tf20_xor(j + 1u, one);
            float kf = __uint2float_rn(y >> 9);
            cnt += (kf < p23);
        }
        {
            float p23 = x4.z * s4.z;
            unsigned int y = tf20_xor(j + 2u, one);
            float kf = __uint2float_rn(y >> 9);
            cnt += (kf < p23);
        }
        {
            float p23 = x4.w * s4.w;
            unsigned int y = tf20_xor(j + 3u, one);
            float kf = __uint2float_rn(y >> 9);
            cnt += (kf < p23);
        }
    }

    // warp-level sum of the 32 partial counts
#pragma unroll
    for (int off = 16; off; off >>= 1)
        cnt += __shfl_xor_sync(0xffffffffu, cnt, off);

    if (lane == 0)
        out[b * OUT_DIM + o] = (float)cnt + bo;
}

extern "C" void kernel_launch(void* const* d_in, const int* in_sizes, int n_in,
                              void* d_out, int out_size) {
    const float* input  = (const float*)d_in[0];
    const float* weight = (const float*)d_in[1];
    const float* bias   = (const float*)d_in[2];
    const float* x0     = (const float*)d_in[3];
    const float* dx     = (const float*)d_in[4];
    const float* a      = (const float*)d_in[5];
    const float* d      = (const float*)d_in[6];
    float* out = (float*)d_out;

    prep_kernel<<<(OUT_DIM * IN_DIM) / 256, 256>>>(weight, x0, dx, a, d);
    synapse_kernel<<<B_DIM * (OUT_DIM / 8), 256>>>(input, bias, out);
}